// round 16
// baseline (speedup 1.0000x reference)
#include <cuda_runtime.h>
#include <cuda_fp16.h>
#include <math.h>

#define N_NODES 80000
#define N_EDGES 1280000
#define IN_C    128
#define HID_C   64
#define OUT_C   40

#define SCAN_CHUNK 1024
#define NCHUNK ((N_NODES + SCAN_CHUNK - 1) / SCAN_CHUNK)   // 79

typedef unsigned long long u64;

__device__ __forceinline__ unsigned h2_bits(__half2 h) {
    return *reinterpret_cast<unsigned*>(&h);
}

// ---------------- static device scratch (no allocations allowed) ----------
// g_deg / g_pack: zero at first use (static zero-init); re-zeroed each call
// by k_gemm2's tail (runs strictly after their consumers k_hist / k_scan).
__device__ __half g_h1[N_NODES * HID_C];    // x @ W1          (fp16, gathered)
__device__ float  g_a1[N_NODES * HID_C];    // relu(agg(h1))   (fp32, dense)
__device__ __half g_h2[N_NODES * OUT_C];    // a1 @ W2         (fp16, gathered)
__device__ int    g_deg[N_NODES];
__device__ int    g_off[N_NODES + 1];
__device__ int    g_cur[N_NODES];
__device__ int    g_csr_src[N_EDGES];
__device__ u64    g_pack[NCHUNK];           // lookback: (flag<<32)|value

// ============ branch A: CSR build (R15-proven) ============================

__global__ void k_hist(const int* __restrict__ ei) {
    int t = blockIdx.x * blockDim.x + threadIdx.x;
    if (t < N_EDGES / 8) {
        const int4* dv = (const int4*)(ei + N_EDGES);
        int4 d0 = dv[2 * t];
        int4 d1 = dv[2 * t + 1];
        atomicAdd(&g_deg[d0.x], 1);     // no return use -> REDG (fast)
        atomicAdd(&g_deg[d0.y], 1);
        atomicAdd(&g_deg[d0.z], 1);
        atomicAdd(&g_deg[d0.w], 1);
        atomicAdd(&g_deg[d1.x], 1);
        atomicAdd(&g_deg[d1.y], 1);
        atomicAdd(&g_deg[d1.z], 1);
        atomicAdd(&g_deg[d1.w], 1);
    }
}

__device__ __forceinline__ int block_scan_excl(int v, int* smem32) {
    int lane = threadIdx.x & 31;
    int wid  = threadIdx.x >> 5;
    int nw   = blockDim.x >> 5;
    int s = v;
#pragma unroll
    for (int d = 1; d < 32; d <<= 1) {
        int t = __shfl_up_sync(0xffffffffu, s, d);
        if (lane >= d) s += t;
    }
    if (lane == 31) smem32[wid] = s;
    __syncthreads();
    if (wid == 0) {
        int ws = (lane < nw) ? smem32[lane] : 0;
        int ss = ws;
#pragma unroll
        for (int d = 1; d < 32; d <<= 1) {
            int t = __shfl_up_sync(0xffffffffu, ss, d);
            if (lane >= d) ss += t;
        }
        smem32[lane] = ss - ws;
    }
    __syncthreads();
    return smem32[wid] + (s - v);
}

__global__ __launch_bounds__(SCAN_CHUNK) void k_scan() {   // NCHUNK blocks
    __shared__ int sm[32];
    __shared__ int s_total;
    __shared__ int s_base;

    int b = blockIdx.x;
    int i = b * SCAN_CHUNK + threadIdx.x;
    int v = (i < N_NODES) ? g_deg[i] : 0;
    int ex = block_scan_excl(v, sm);
    if (threadIdx.x == SCAN_CHUNK - 1) s_total = ex + v;
    __syncthreads();
    int total = s_total;

    if (threadIdx.x < 32) {
        int lane = threadIdx.x;
        int base = 0;
        if (b == 0) {
            if (lane == 0) {
                __threadfence();
                atomicExch(&g_pack[0], (2ull << 32) | (unsigned)total);
            }
        } else {
            if (lane == 0) {
                __threadfence();
                atomicExch(&g_pack[b], (1ull << 32) | (unsigned)total);
            }
            int p = b - 1;
            bool done = false;
            while (!done) {
                int idx = p - lane;
                u64 w = 0;
                if (idx >= 0) {
                    do { w = atomicAdd(&g_pack[idx], 0ull); } while ((w >> 32) == 0);
                }
                int f = (int)(w >> 32);
                int val = (int)(w & 0xffffffffu);
                unsigned pm = __ballot_sync(0xffffffffu, idx >= 0 && f == 2);
                int cut;
                if (pm) { cut = __ffs(pm) - 1; done = true; }
                else    { cut = (p >= 31) ? 31 : p; }
                int contrib = (lane <= cut && idx >= 0) ? val : 0;
#pragma unroll
                for (int d = 16; d > 0; d >>= 1)
                    contrib += __shfl_xor_sync(0xffffffffu, contrib, d);
                base += contrib;
                p -= 32;
                if (p < 0) done = true;
            }
            if (lane == 0) {
                __threadfence();
                atomicExch(&g_pack[b], (2ull << 32) | (unsigned)(base + total));
                s_base = base;
            }
        }
        if (lane == 0 && b == 0) s_base = 0;
    }
    __syncthreads();
    int base = s_base;
    if (i < N_NODES) {
        g_off[i] = base + ex;
        g_cur[i] = base + ex;
    }
    if (b == NCHUNK - 1 && threadIdx.x == 0) g_off[N_NODES] = N_EDGES;
}

__global__ void k_fill(const int* __restrict__ ei) {
    int t = blockIdx.x * blockDim.x + threadIdx.x;
    if (t < N_EDGES / 8) {
        const int4* sv = (const int4*)ei;
        const int4* dv = (const int4*)(ei + N_EDGES);
        int4 s0 = sv[2 * t];
        int4 s1 = sv[2 * t + 1];
        int4 d0 = dv[2 * t];
        int4 d1 = dv[2 * t + 1];
        g_csr_src[atomicAdd(&g_cur[d0.x], 1)] = s0.x;
        g_csr_src[atomicAdd(&g_cur[d0.y], 1)] = s0.y;
        g_csr_src[atomicAdd(&g_cur[d0.z], 1)] = s0.z;
        g_csr_src[atomicAdd(&g_cur[d0.w], 1)] = s0.w;
        g_csr_src[atomicAdd(&g_cur[d1.x], 1)] = s1.x;
        g_csr_src[atomicAdd(&g_cur[d1.y], 1)] = s1.y;
        g_csr_src[atomicAdd(&g_cur[d1.z], 1)] = s1.z;
        g_csr_src[atomicAdd(&g_cur[d1.w], 1)] = s1.w;
    }
}

// ============ branch B: GEMM1 (h1 = x @ W1, fp32 math, fp16 store) ========

__global__ __launch_bounds__(256) void k_gemm1(const float* __restrict__ x,
                                               const float* __restrict__ W1) {
    __shared__ float Ws[IN_C * HID_C];   // 32 KB
    for (int i = threadIdx.x; i < IN_C * HID_C; i += blockDim.x) Ws[i] = W1[i];
    __syncthreads();

    int v = blockIdx.x * blockDim.x + threadIdx.x;
    if (v >= N_NODES) return;

    float acc[HID_C];
#pragma unroll
    for (int j = 0; j < HID_C; j++) acc[j] = 0.f;

    const float4* xr = (const float4*)(x + (size_t)v * IN_C);
#pragma unroll 2
    for (int k4 = 0; k4 < IN_C / 4; k4++) {
        float4 xv = xr[k4];
        int kb = k4 * 4;
#pragma unroll
        for (int c = 0; c < 4; c++) {
            float xc = (c == 0) ? xv.x : (c == 1) ? xv.y : (c == 2) ? xv.z : xv.w;
            const float4* wr = (const float4*)(Ws + (kb + c) * HID_C);
#pragma unroll
            for (int j4 = 0; j4 < HID_C / 4; j4++) {
                float4 w = wr[j4];
                acc[4 * j4 + 0] += xc * w.x;
                acc[4 * j4 + 1] += xc * w.y;
                acc[4 * j4 + 2] += xc * w.z;
                acc[4 * j4 + 3] += xc * w.w;
            }
        }
    }
    uint4* o = (uint4*)(g_h1 + (size_t)v * HID_C);
#pragma unroll
    for (int j8 = 0; j8 < HID_C / 8; j8++) {
        __half2 p0 = __float22half2_rn(make_float2(acc[8*j8+0], acc[8*j8+1]));
        __half2 p1 = __float22half2_rn(make_float2(acc[8*j8+2], acc[8*j8+3]));
        __half2 p2 = __float22half2_rn(make_float2(acc[8*j8+4], acc[8*j8+5]));
        __half2 p3 = __float22half2_rn(make_float2(acc[8*j8+6], acc[8*j8+7]));
        o[j8] = make_uint4(h2_bits(p0), h2_bits(p1), h2_bits(p2), h2_bits(p3));
    }
}

// ============ SpMM1 + relu (R15-proven) ===================================

__global__ void k_spmm1() {
    int gw = (blockIdx.x * blockDim.x + threadIdx.x) >> 5;
    if (gw >= N_NODES) return;
    int lane = threadIdx.x & 31;
    int beg = g_off[gw], end = g_off[gw + 1];

    const __half2* h1v = (const __half2*)g_h1;   // 32 half2 per row
    float2 acc = make_float2(0.f, 0.f);
#pragma unroll 8
    for (int idx = beg; idx < end; idx++) {
        int s = __ldg(&g_csr_src[idx]);          // uniform across warp
        __half2 hv = __ldg(&h1v[(size_t)s * (HID_C / 2) + lane]);
        float2 f = __half22float2(hv);
        acc.x += f.x;
        acc.y += f.y;
    }
    ((float2*)g_a1)[(size_t)gw * (HID_C / 2) + lane] =
        make_float2(fmaxf(acc.x, 0.f), fmaxf(acc.y, 0.f));
}

// ============ GEMM2 v3: 4 threads per node, 10 cols each ==================
// R13 proved the occupancy lever (30us -> ~16us at 2 thr/node). Extend:
// 10 accumulators/thread, 4 sibling threads share the a1 row (L1-merged).
// W2 strip offsets are 40B (8B-aligned) -> float2 loads; stores 5x uint.
// Tail re-zeroes deg/pack for the NEXT call.

__global__ __launch_bounds__(256) void k_gemm2(const float* __restrict__ W2) {
    __shared__ float Ws[HID_C * OUT_C];  // 10.25 KB
    for (int i = threadIdx.x; i < HID_C * OUT_C; i += blockDim.x) Ws[i] = W2[i];
    __syncthreads();

    int t = blockIdx.x * blockDim.x + threadIdx.x;

    // re-zero CSR state for next call (grid = 320K threads >= N_NODES)
    if (t < N_NODES) g_deg[t] = 0;
    if (t < NCHUNK)  g_pack[t] = 0ull;

    int v = t >> 2;                      // node
    int q = t & 3;                       // col group: [10q, 10q+10)
    if (v >= N_NODES) return;

    float acc[OUT_C / 4];                // 10 accumulators
#pragma unroll
    for (int j = 0; j < OUT_C / 4; j++) acc[j] = 0.f;

    const float4* ar = (const float4*)(g_a1 + (size_t)v * HID_C);
    const float* wbase = Ws + q * (OUT_C / 4);      // 10-float col offset (8B-aligned)
#pragma unroll 2
    for (int k4 = 0; k4 < HID_C / 4; k4++) {
        float4 av = ar[k4];
        int kb = k4 * 4;
#pragma unroll
        for (int c = 0; c < 4; c++) {
            float ac = (c == 0) ? av.x : (c == 1) ? av.y : (c == 2) ? av.z : av.w;
            const float2* wr = (const float2*)(wbase + (kb + c) * OUT_C);
#pragma unroll
            for (int j2 = 0; j2 < 5; j2++) {     // 10 cols = 5 float2
                float2 w = wr[j2];
                acc[2 * j2 + 0] += ac * w.x;
                acc[2 * j2 + 1] += ac * w.y;
            }
        }
    }
    // pack 10 floats -> 5 half2 words; byte offset v*80 + q*20 (4B-aligned)
    unsigned* row = (unsigned*)(g_h2 + (size_t)v * OUT_C + q * (OUT_C / 4));
#pragma unroll
    for (int j = 0; j < 5; j++) {
        __half2 h = __float22half2_rn(make_float2(acc[2*j], acc[2*j+1]));
        row[j] = h2_bits(h);
    }
}

// ============ SpMM2 + log_softmax (R15-proven) ============================

__global__ void k_spmm2_lsm(float* __restrict__ out) {
    int gw = (blockIdx.x * blockDim.x + threadIdx.x) >> 5;
    if (gw >= N_NODES) return;
    int lane = threadIdx.x & 31;
    int beg = g_off[gw], end = g_off[gw + 1];

    const __half2* h2v = (const __half2*)g_h2;   // 20 half2 per row
    bool active = lane < (OUT_C / 2);
    int cl = active ? lane : 0;

    float2 acc = make_float2(0.f, 0.f);
#pragma unroll 8
    for (int idx = beg; idx < end; idx++) {
        int s = __ldg(&g_csr_src[idx]);
        __half2 hv = __ldg(&h2v[(size_t)s * (OUT_C / 2) + cl]);
        float2 f = __half22float2(hv);
        acc.x += f.x;
        acc.y += f.y;
    }

    float m = active ? fmaxf(acc.x, acc.y) : -INFINITY;
#pragma unroll
    for (int d = 16; d > 0; d >>= 1) m = fmaxf(m, __shfl_xor_sync(0xffffffffu, m, d));
    float sum = active ? (expf(acc.x - m) + expf(acc.y - m)) : 0.f;
#pragma unroll
    for (int d = 16; d > 0; d >>= 1) sum += __shfl_xor_sync(0xffffffffu, sum, d);
    float lse = logf(sum);
    if (active) {
        ((float2*)out)[(size_t)gw * (OUT_C / 2) + lane] =
            make_float2(acc.x - m - lse, acc.y - m - lse);
    }
}

// ---------------- launch: forked graph ------------------------------------
// branch A (stream 0):  hist -> scan -> fill
// branch B (side strm): gemm1
// join -> spmm1 -> gemm2(+re-zero) -> spmm2_lsm

extern "C" void kernel_launch(void* const* d_in, const int* in_sizes, int n_in,
                              void* d_out, int out_size) {
    const float* x  = (const float*)d_in[0];     // [80000,128]
    const int*   ei = (const int*)d_in[1];       // [2,1280000]
    const float* W1 = (const float*)d_in[2];     // [128,64]
    const float* W2 = (const float*)d_in[3];     // [64,40]
    float* out = (float*)d_out;                  // [80000,40]

    const int TB = 256;

    cudaStream_t sB;
    cudaEvent_t eFork, eJoin;
    cudaStreamCreateWithFlags(&sB, cudaStreamNonBlocking);
    cudaEventCreateWithFlags(&eFork, cudaEventDisableTiming);
    cudaEventCreateWithFlags(&eJoin, cudaEventDisableTiming);

    // fork
    cudaEventRecord(eFork, 0);
    cudaStreamWaitEvent(sB, eFork, 0);

    // branch B: GEMM1 on side stream
    k_gemm1<<<(N_NODES + TB - 1) / TB, TB, 0, sB>>>(x, W1);
    cudaEventRecord(eJoin, sB);

    // branch A: CSR build on main stream (8 edges/thread)
    k_hist<<<(N_EDGES / 8 + TB - 1) / TB, TB>>>(ei);
    k_scan<<<NCHUNK, SCAN_CHUNK>>>();
    k_fill<<<(N_EDGES / 8 + TB - 1) / TB, TB>>>(ei);

    // join: spmm1 needs both h1 and CSR
    cudaStreamWaitEvent(0, eJoin, 0);

    k_spmm1<<<(N_NODES * 32 + TB - 1) / TB, TB>>>();
    k_gemm2<<<(N_NODES * 4 + TB - 1) / TB, TB>>>(W2);
    k_spmm2_lsm<<<(N_NODES * 32 + TB - 1) / TB, TB>>>(out);
}

// round 17
// speedup vs baseline: 1.0466x; 1.0466x over previous
#include <cuda_runtime.h>
#include <cuda_fp16.h>
#include <math.h>

#define N_NODES 80000
#define N_EDGES 1280000
#define IN_C    128
#define HID_C   64
#define OUT_C   40
#define HALF_N  (N_NODES / 2)

#define SCAN_CHUNK 1024
#define NCHUNK ((N_NODES + SCAN_CHUNK - 1) / SCAN_CHUNK)   // 79

typedef unsigned long long u64;

__device__ __forceinline__ unsigned h2_bits(__half2 h) {
    return *reinterpret_cast<unsigned*>(&h);
}

// ---------------- static device scratch (no allocations allowed) ----------
// g_deg / g_pack: zero at first use (static zero-init); re-zeroed each call
// by k_gemm2(h0)'s tail (runs strictly after their consumers hist / scan).
__device__ __half g_h1[N_NODES * HID_C];    // x @ W1          (fp16, gathered)
__device__ float  g_a1[N_NODES * HID_C];    // relu(agg(h1))   (fp32, dense)
__device__ __half g_h2[N_NODES * OUT_C];    // a1 @ W2         (fp16, gathered)
__device__ int    g_deg[N_NODES];
__device__ int    g_off[N_NODES + 1];
__device__ int    g_cur[N_NODES];
__device__ int    g_csr_src[N_EDGES];
__device__ u64    g_pack[NCHUNK];           // lookback: (flag<<32)|value

// ============ branch A: CSR build (R15-proven) ============================

__global__ void k_hist(const int* __restrict__ ei) {
    int t = blockIdx.x * blockDim.x + threadIdx.x;
    if (t < N_EDGES / 8) {
        const int4* dv = (const int4*)(ei + N_EDGES);
        int4 d0 = dv[2 * t];
        int4 d1 = dv[2 * t + 1];
        atomicAdd(&g_deg[d0.x], 1);     // no return use -> REDG (fast)
        atomicAdd(&g_deg[d0.y], 1);
        atomicAdd(&g_deg[d0.z], 1);
        atomicAdd(&g_deg[d0.w], 1);
        atomicAdd(&g_deg[d1.x], 1);
        atomicAdd(&g_deg[d1.y], 1);
        atomicAdd(&g_deg[d1.z], 1);
        atomicAdd(&g_deg[d1.w], 1);
    }
}

__device__ __forceinline__ int block_scan_excl(int v, int* smem32) {
    int lane = threadIdx.x & 31;
    int wid  = threadIdx.x >> 5;
    int nw   = blockDim.x >> 5;
    int s = v;
#pragma unroll
    for (int d = 1; d < 32; d <<= 1) {
        int t = __shfl_up_sync(0xffffffffu, s, d);
        if (lane >= d) s += t;
    }
    if (lane == 31) smem32[wid] = s;
    __syncthreads();
    if (wid == 0) {
        int ws = (lane < nw) ? smem32[lane] : 0;
        int ss = ws;
#pragma unroll
        for (int d = 1; d < 32; d <<= 1) {
            int t = __shfl_up_sync(0xffffffffu, ss, d);
            if (lane >= d) ss += t;
        }
        smem32[lane] = ss - ws;
    }
    __syncthreads();
    return smem32[wid] + (s - v);
}

__global__ __launch_bounds__(SCAN_CHUNK) void k_scan() {   // NCHUNK blocks
    __shared__ int sm[32];
    __shared__ int s_total;
    __shared__ int s_base;

    int b = blockIdx.x;
    int i = b * SCAN_CHUNK + threadIdx.x;
    int v = (i < N_NODES) ? g_deg[i] : 0;
    int ex = block_scan_excl(v, sm);
    if (threadIdx.x == SCAN_CHUNK - 1) s_total = ex + v;
    __syncthreads();
    int total = s_total;

    if (threadIdx.x < 32) {
        int lane = threadIdx.x;
        int base = 0;
        if (b == 0) {
            if (lane == 0) {
                __threadfence();
                atomicExch(&g_pack[0], (2ull << 32) | (unsigned)total);
            }
        } else {
            if (lane == 0) {
                __threadfence();
                atomicExch(&g_pack[b], (1ull << 32) | (unsigned)total);
            }
            int p = b - 1;
            bool done = false;
            while (!done) {
                int idx = p - lane;
                u64 w = 0;
                if (idx >= 0) {
                    do { w = atomicAdd(&g_pack[idx], 0ull); } while ((w >> 32) == 0);
                }
                int f = (int)(w >> 32);
                int val = (int)(w & 0xffffffffu);
                unsigned pm = __ballot_sync(0xffffffffu, idx >= 0 && f == 2);
                int cut;
                if (pm) { cut = __ffs(pm) - 1; done = true; }
                else    { cut = (p >= 31) ? 31 : p; }
                int contrib = (lane <= cut && idx >= 0) ? val : 0;
#pragma unroll
                for (int d = 16; d > 0; d >>= 1)
                    contrib += __shfl_xor_sync(0xffffffffu, contrib, d);
                base += contrib;
                p -= 32;
                if (p < 0) done = true;
            }
            if (lane == 0) {
                __threadfence();
                atomicExch(&g_pack[b], (2ull << 32) | (unsigned)(base + total));
                s_base = base;
            }
        }
        if (lane == 0 && b == 0) s_base = 0;
    }
    __syncthreads();
    int base = s_base;
    if (i < N_NODES) {
        g_off[i] = base + ex;
        g_cur[i] = base + ex;
    }
    if (b == NCHUNK - 1 && threadIdx.x == 0) g_off[N_NODES] = N_EDGES;
}

__global__ void k_fill(const int* __restrict__ ei) {
    int t = blockIdx.x * blockDim.x + threadIdx.x;
    if (t < N_EDGES / 8) {
        const int4* sv = (const int4*)ei;
        const int4* dv = (const int4*)(ei + N_EDGES);
        int4 s0 = sv[2 * t];
        int4 s1 = sv[2 * t + 1];
        int4 d0 = dv[2 * t];
        int4 d1 = dv[2 * t + 1];
        g_csr_src[atomicAdd(&g_cur[d0.x], 1)] = s0.x;
        g_csr_src[atomicAdd(&g_cur[d0.y], 1)] = s0.y;
        g_csr_src[atomicAdd(&g_cur[d0.z], 1)] = s0.z;
        g_csr_src[atomicAdd(&g_cur[d0.w], 1)] = s0.w;
        g_csr_src[atomicAdd(&g_cur[d1.x], 1)] = s1.x;
        g_csr_src[atomicAdd(&g_cur[d1.y], 1)] = s1.y;
        g_csr_src[atomicAdd(&g_cur[d1.z], 1)] = s1.z;
        g_csr_src[atomicAdd(&g_cur[d1.w], 1)] = s1.w;
    }
}

// ============ branch B: GEMM1 (h1 = x @ W1, fp32 math, fp16 store) ========

__global__ __launch_bounds__(256) void k_gemm1(const float* __restrict__ x,
                                               const float* __restrict__ W1) {
    __shared__ float Ws[IN_C * HID_C];   // 32 KB
    for (int i = threadIdx.x; i < IN_C * HID_C; i += blockDim.x) Ws[i] = W1[i];
    __syncthreads();

    int v = blockIdx.x * blockDim.x + threadIdx.x;
    if (v >= N_NODES) return;

    float acc[HID_C];
#pragma unroll
    for (int j = 0; j < HID_C; j++) acc[j] = 0.f;

    const float4* xr = (const float4*)(x + (size_t)v * IN_C);
#pragma unroll 2
    for (int k4 = 0; k4 < IN_C / 4; k4++) {
        float4 xv = xr[k4];
        int kb = k4 * 4;
#pragma unroll
        for (int c = 0; c < 4; c++) {
            float xc = (c == 0) ? xv.x : (c == 1) ? xv.y : (c == 2) ? xv.z : xv.w;
            const float4* wr = (const float4*)(Ws + (kb + c) * HID_C);
#pragma unroll
            for (int j4 = 0; j4 < HID_C / 4; j4++) {
                float4 w = wr[j4];
                acc[4 * j4 + 0] += xc * w.x;
                acc[4 * j4 + 1] += xc * w.y;
                acc[4 * j4 + 2] += xc * w.z;
                acc[4 * j4 + 3] += xc * w.w;
            }
        }
    }
    uint4* o = (uint4*)(g_h1 + (size_t)v * HID_C);
#pragma unroll
    for (int j8 = 0; j8 < HID_C / 8; j8++) {
        __half2 p0 = __float22half2_rn(make_float2(acc[8*j8+0], acc[8*j8+1]));
        __half2 p1 = __float22half2_rn(make_float2(acc[8*j8+2], acc[8*j8+3]));
        __half2 p2 = __float22half2_rn(make_float2(acc[8*j8+4], acc[8*j8+5]));
        __half2 p3 = __float22half2_rn(make_float2(acc[8*j8+6], acc[8*j8+7]));
        o[j8] = make_uint4(h2_bits(p0), h2_bits(p1), h2_bits(p2), h2_bits(p3));
    }
}

// ============ SpMM1 + relu (R15-proven body, node_base param) =============

__global__ void k_spmm1(int node_base) {
    int gl = (blockIdx.x * blockDim.x + threadIdx.x) >> 5;
    if (gl >= HALF_N) return;
    int gw = node_base + gl;
    int lane = threadIdx.x & 31;
    int beg = g_off[gw], end = g_off[gw + 1];

    const __half2* h1v = (const __half2*)g_h1;   // 32 half2 per row
    float2 acc = make_float2(0.f, 0.f);
#pragma unroll 8
    for (int idx = beg; idx < end; idx++) {
        int s = __ldg(&g_csr_src[idx]);          // uniform across warp
        __half2 hv = __ldg(&h1v[(size_t)s * (HID_C / 2) + lane]);
        float2 f = __half22float2(hv);
        acc.x += f.x;
        acc.y += f.y;
    }
    ((float2*)g_a1)[(size_t)gw * (HID_C / 2) + lane] =
        make_float2(fmaxf(acc.x, 0.f), fmaxf(acc.y, 0.f));
}

// ============ GEMM2 (R13-proven 2-thr split, node_base param) =============
// h0 call additionally re-zeroes deg/pack for the NEXT call (its 80K threads
// exactly cover N_NODES; deg/pack have no remaining readers this call).

__global__ __launch_bounds__(256) void k_gemm2(const float* __restrict__ W2,
                                               int node_base, int do_zero) {
    __shared__ float Ws[HID_C * OUT_C];  // 10.25 KB
    for (int i = threadIdx.x; i < HID_C * OUT_C; i += blockDim.x) Ws[i] = W2[i];
    __syncthreads();

    int t = blockIdx.x * blockDim.x + threadIdx.x;

    if (do_zero) {
        if (t < N_NODES) g_deg[t] = 0;   // 2*HALF_N threads == N_NODES
        if (t < NCHUNK)  g_pack[t] = 0ull;
    }

    int vl = t >> 1;                     // local node
    int half = t & 1;                    // col group: [0,20) or [20,40)
    if (vl >= HALF_N) return;
    int v = node_base + vl;

    float acc[OUT_C / 2];                // 20 accumulators
#pragma unroll
    for (int j = 0; j < OUT_C / 2; j++) acc[j] = 0.f;

    const float4* ar = (const float4*)(g_a1 + (size_t)v * HID_C);
    const float* wbase = Ws + half * (OUT_C / 2);   // 20-float col offset
#pragma unroll 2
    for (int k4 = 0; k4 < HID_C / 4; k4++) {
        float4 av = ar[k4];
        int kb = k4 * 4;
#pragma unroll
        for (int c = 0; c < 4; c++) {
            float ac = (c == 0) ? av.x : (c == 1) ? av.y : (c == 2) ? av.z : av.w;
            const float4* wr = (const float4*)(wbase + (kb + c) * OUT_C);
#pragma unroll
            for (int j4 = 0; j4 < 5; j4++) {     // 20 cols = 5 float4
                float4 w = wr[j4];
                acc[4 * j4 + 0] += ac * w.x;
                acc[4 * j4 + 1] += ac * w.y;
                acc[4 * j4 + 2] += ac * w.z;
                acc[4 * j4 + 3] += ac * w.w;
            }
        }
    }
    // pack 20 floats -> 10 half2 words -> 5 x uint2 stores (off 8B-aligned)
    unsigned up[OUT_C / 4];              // 10 words
#pragma unroll
    for (int j = 0; j < OUT_C / 4; j++) {
        __half2 h = __float22half2_rn(make_float2(acc[2*j], acc[2*j+1]));
        up[j] = h2_bits(h);
    }
    uint2* row = (uint2*)(g_h2 + (size_t)v * OUT_C + half * (OUT_C / 2));
#pragma unroll
    for (int q = 0; q < 5; q++)
        row[q] = make_uint2(up[2*q], up[2*q+1]);
}

// ============ SpMM2 + log_softmax (R15-proven) ============================

__global__ void k_spmm2_lsm(float* __restrict__ out) {
    int gw = (blockIdx.x * blockDim.x + threadIdx.x) >> 5;
    if (gw >= N_NODES) return;
    int lane = threadIdx.x & 31;
    int beg = g_off[gw], end = g_off[gw + 1];

    const __half2* h2v = (const __half2*)g_h2;   // 20 half2 per row
    bool active = lane < (OUT_C / 2);
    int cl = active ? lane : 0;

    float2 acc = make_float2(0.f, 0.f);
#pragma unroll 8
    for (int idx = beg; idx < end; idx++) {
        int s = __ldg(&g_csr_src[idx]);
        __half2 hv = __ldg(&h2v[(size_t)s * (OUT_C / 2) + cl]);
        float2 f = __half22float2(hv);
        acc.x += f.x;
        acc.y += f.y;
    }

    float m = active ? fmaxf(acc.x, acc.y) : -INFINITY;
#pragma unroll
    for (int d = 16; d > 0; d >>= 1) m = fmaxf(m, __shfl_xor_sync(0xffffffffu, m, d));
    float sum = active ? (expf(acc.x - m) + expf(acc.y - m)) : 0.f;
#pragma unroll
    for (int d = 16; d > 0; d >>= 1) sum += __shfl_xor_sync(0xffffffffu, sum, d);
    float lse = logf(sum);
    if (active) {
        ((float2*)out)[(size_t)gw * (OUT_C / 2) + lane] =
            make_float2(acc.x - m - lse, acc.y - m - lse);
    }
}

// ---------------- launch: forked + pipelined graph -------------------------
// A (main): hist -> scan -> fill
// B (side): gemm1
// join; then pipeline by node halves:
//   main: spmm1_h0 -> [e0] -> spmm1_h1 -> gemm2_h1 -> [wait eg0] -> spmm2
//   side: wait e0 -> gemm2_h0(+re-zero) -> [eg0]
// (spmm1_h1 is bandwidth-bound, gemm2_h0 FMA-bound -> complementary overlap)

extern "C" void kernel_launch(void* const* d_in, const int* in_sizes, int n_in,
                              void* d_out, int out_size) {
    const float* x  = (const float*)d_in[0];     // [80000,128]
    const int*   ei = (const int*)d_in[1];       // [2,1280000]
    const float* W1 = (const float*)d_in[2];     // [128,64]
    const float* W2 = (const float*)d_in[3];     // [64,40]
    float* out = (float*)d_out;                  // [80000,40]

    const int TB = 256;
    const int SPMM1_BLK = (HALF_N * 32 + TB - 1) / TB;   // 5000
    const int GEMM2_BLK = (HALF_N * 2 + TB - 1) / TB;    // 313

    cudaStream_t sB;
    cudaEvent_t eFork, eG1, e0, eg0;
    cudaStreamCreateWithFlags(&sB, cudaStreamNonBlocking);
    cudaEventCreateWithFlags(&eFork, cudaEventDisableTiming);
    cudaEventCreateWithFlags(&eG1,   cudaEventDisableTiming);
    cudaEventCreateWithFlags(&e0,    cudaEventDisableTiming);
    cudaEventCreateWithFlags(&eg0,   cudaEventDisableTiming);

    // fork
    cudaEventRecord(eFork, 0);
    cudaStreamWaitEvent(sB, eFork, 0);

    // side: GEMM1
    k_gemm1<<<(N_NODES + TB - 1) / TB, TB, 0, sB>>>(x, W1);
    cudaEventRecord(eG1, sB);

    // main: CSR build
    k_hist<<<(N_EDGES / 8 + TB - 1) / TB, TB>>>(ei);
    k_scan<<<NCHUNK, SCAN_CHUNK>>>();
    k_fill<<<(N_EDGES / 8 + TB - 1) / TB, TB>>>(ei);

    // join: spmm1 needs h1 + CSR
    cudaStreamWaitEvent(0, eG1, 0);

    // pipelined halves
    k_spmm1<<<SPMM1_BLK, TB>>>(0);
    cudaEventRecord(e0, 0);
    k_spmm1<<<SPMM1_BLK, TB>>>(HALF_N);

    cudaStreamWaitEvent(sB, e0, 0);
    k_gemm2<<<GEMM2_BLK, TB, 0, sB>>>(W2, 0, 1);        // + deg/pack re-zero
    cudaEventRecord(eg0, sB);

    k_gemm2<<<GEMM2_BLK, TB>>>(W2, HALF_N, 0);

    cudaStreamWaitEvent(0, eg0, 0);
    k_spmm2_lsm<<<(N_NODES * 32 + TB - 1) / TB, TB>>>(out);
}